// round 7
// baseline (speedup 1.0000x reference)
#include <cuda_runtime.h>
#include <cuda_fp16.h>

#define D      128
#define H0     64
#define W0     96
#define NPIX0  (H0*W0)        // 6144
#define NPIX_T 8160           // 6144+1536+384+96

__device__ __align__(16) __half g_f1h[NPIX_T * D];   // fp16 channel-last, all levels
__device__ __align__(16) __half g_f2h[NPIX_T * D];   // fp16 channel-last, all levels
__device__ float  g_crd [NPIX_T * 2];
__device__ float  g_tmpA[5376 * 2];                  // x-resized coords, levels 1-3
__device__ unsigned g_ct_prep, g_ct_ca, g_ct_pool, g_ct_cb;

__constant__ int c_HL[4] = {64, 32, 16, 8};
__constant__ int c_WL[4] = {96, 48, 24, 12};
__constant__ int c_PO[4] = {0, 6144, 7680, 8064};
__constant__ int c_OO[4] = {0, 81*6144, 81*7680, 81*8064};

// Block-range layout of the mega kernel (strictly dependency-ordered bids)
#define TR_BLOCKS   1536
#define CA_BLOCKS   90        // (2*6144 + 5376*2 + 255)/256
#define C0_BLOCKS   768       // level-0 corr, 8 px/block
#define PL_BLOCKS   2016      // 2*2016*128/256
#define CB_BLOCKS   16        // (2016*2 + 255)/256
#define C123_BLOCKS 252       // 192+48+12
#define B_CA   (TR_BLOCKS)            // 1536
#define B_C0   (B_CA + CA_BLOCKS)     // 1626
#define B_PL   (B_C0 + C0_BLOCKS)     // 2394
#define B_CB   (B_PL + PL_BLOCKS)     // 4410
#define B_C123 (B_CB + CB_BLOCKS)     // 4426
#define B_END  (B_C123 + C123_BLOCKS) // 4678

// ---------------------------------------------------------------------------
// spin-gate primitives (release: fence-all-threads + bar + one atomicAdd;
// acquire: poll volatile, fence, bar)
// ---------------------------------------------------------------------------
__device__ __forceinline__ void sig(unsigned* c) {
    __threadfence();
    __syncthreads();
    if (threadIdx.x == 0) atomicAdd(c, 1u);
}
__device__ __forceinline__ void wait1(unsigned* c, unsigned t) {
    if (threadIdx.x == 0) {
        while (*(volatile unsigned*)c < t) __nanosleep(64);
        __threadfence();
    }
    __syncthreads();
}
__device__ __forceinline__ void wait2(unsigned* c0, unsigned t0,
                                      unsigned* c1, unsigned t1) {
    if (threadIdx.x == 0) {
        while (*(volatile unsigned*)c0 < t0) __nanosleep(64);
        while (*(volatile unsigned*)c1 < t1) __nanosleep(64);
        __threadfence();
    }
    __syncthreads();
}

__global__ void k_reset() {
    g_ct_prep = 0; g_ct_ca = 0; g_ct_pool = 0; g_ct_cb = 0;
}

// ---------------------------------------------------------------------------
// pooling helper (compile-time taps)
// ---------------------------------------------------------------------------
template<int F>
__device__ __forceinline__ float poolh(const __half* __restrict__ src, int h, int w, int d) {
    float acc = 0.f;
    #pragma unroll
    for (int i = 0; i < F; i++)
        #pragma unroll
        for (int j = 0; j < F; j++)
            acc += __half2float(src[(size_t)((h*F + i) * W0 + (w*F + j)) * D + d]);
    return acc * (1.0f / (F * F));
}

__device__ __forceinline__ float dot8h(float4 a0, float4 a1, float4 hv) {
    const __half2* h = (const __half2*)&hv;
    float2 v0 = __half22float2(h[0]);
    float2 v1 = __half22float2(h[1]);
    float2 v2 = __half22float2(h[2]);
    float2 v3 = __half22float2(h[3]);
    return a0.x*v0.x + a0.y*v0.y + a0.z*v1.x + a0.w*v1.y
         + a1.x*v2.x + a1.y*v2.y + a1.z*v3.x + a1.w*v3.y;
}

// ---------------------------------------------------------------------------
// corr body: 8 px/block, warp<->pixel, 8-lane dot groups, ALU offsets (R5)
// ---------------------------------------------------------------------------
#define TILE 8
__device__ __forceinline__ void corr_part(int l, int pix0, float* __restrict__ out,
                                          char* s_raw) {
    int Hl = c_HL[l], Wl = c_WL[l];
    int pixoff = c_PO[l];
    int HW = Hl * Wl;

    int tid   = threadIdx.x;
    int lane  = tid & 31, warp = tid >> 5;
    int lane8 = lane & 7, grp = lane >> 3;

    float* gsh = (float*)s_raw;      // 800 floats
    float* fxs = gsh + 800;          // 8
    float* fys = fxs + 8;            // 8
    int*   bxs = (int*)(fys + 8);    // 8
    int*   bys = bxs + 8;            // 8

    int pix = pix0 + warp;

    const __half* f1row = g_f1h + (size_t)(pixoff + pix) * D;
    float4 ha = *(const float4*)(f1row + lane8 * 8);
    float4 hb = *(const float4*)(f1row + 64 + lane8 * 8);
    float4 a0, a1, a2, a3;
    {
        const __half2* pa = (const __half2*)&ha;
        float2 q0 = __half22float2(pa[0]), q1 = __half22float2(pa[1]);
        float2 q2 = __half22float2(pa[2]), q3 = __half22float2(pa[3]);
        a0 = make_float4(q0.x, q0.y, q1.x, q1.y);
        a1 = make_float4(q2.x, q2.y, q3.x, q3.y);
        const __half2* pb = (const __half2*)&hb;
        q0 = __half22float2(pb[0]); q1 = __half22float2(pb[1]);
        q2 = __half22float2(pb[2]); q3 = __half22float2(pb[3]);
        a2 = make_float4(q0.x, q0.y, q1.x, q1.y);
        a3 = make_float4(q2.x, q2.y, q3.x, q3.y);
    }

    float cx = 0.f, cy = 0.f;
    if (lane == 0) {
        cx = g_crd[(pixoff + pix) * 2];
        cy = g_crd[(pixoff + pix) * 2 + 1];
    }
    cx = __shfl_sync(0xffffffffu, cx, 0);
    cy = __shfl_sync(0xffffffffu, cy, 0);
    float flx = floorf(cx), fly = floorf(cy);
    int bx = (int)flx, by = (int)fly;
    if (lane == 0) {
        bxs[warp] = bx; bys[warp] = by;
        fxs[warp] = cx - flx; fys[warp] = cy - fly;
    }

    const __half* f2lane = g_f2h + (size_t)pixoff * D + lane8 * 8;
    float* gsh100 = gsh + warp * 100;

    #pragma unroll 5
    for (int i = 0; i < 25; i++) {
        int pos = i * 4 + grp;
        int u = (pos * 205) >> 11;       // pos / 10
        int t = pos - u * 10;            // pos % 10
        int px = min(max(bx + t - 4, 0), Wl - 1);
        int py = min(max(by + u - 4, 0), Hl - 1);
        const __half* row = f2lane + (py * Wl + px) * D;
        float4 h0 = *(const float4*)(row);
        float4 h1 = *(const float4*)(row + 64);
        float s = dot8h(a0, a1, h0) + dot8h(a2, a3, h1);
        s += __shfl_xor_sync(0xffffffffu, s, 4);
        s += __shfl_xor_sync(0xffffffffu, s, 2);
        s += __shfl_xor_sync(0xffffffffu, s, 1);
        if (lane8 == 0) gsh100[pos] = s;
    }
    __syncthreads();

    #pragma unroll
    for (int idx = tid; idx < 81 * TILE; idx += 256) {
        int k = idx >> 3;
        int j = idx & (TILE - 1);
        int adx = k / 9;
        int bdy = k - adx * 9;
        int t0 = bxs[j] + adx - 4;
        int u0 = bys[j] + bdy - 4;
        float wx1 = (t0 < 0 || t0 >= Wl - 1) ? 0.f : fxs[j];
        float wy1 = (u0 < 0 || u0 >= Hl - 1) ? 0.f : fys[j];
        float wx0 = 1.f - wx1, wy0 = 1.f - wy1;
        const float* g = gsh + j * 100 + bdy * 10 + adx;
        float c = wy0 * (wx0 * g[0]  + wx1 * g[1])
                + wy1 * (wx0 * g[10] + wx1 * g[11]);
        out[c_OO[l] + k * HW + pix0 + j] = c * 0.08838834764831845f; // 1/sqrt(128)
    }
}

// ---------------------------------------------------------------------------
// The mega kernel
// ---------------------------------------------------------------------------
__global__ void __launch_bounds__(256) k_all(const float* __restrict__ f1,
                                             const float* __restrict__ f2,
                                             const float* __restrict__ crd,
                                             float* __restrict__ out) {
    __shared__ __align__(16) char s_raw[4352];
    int b = blockIdx.x;

    if (b < TR_BLOCKS) {
        // ---- transpose (D,HW)->(HW,D) fp32 -> fp16 ----
        float* tile = (float*)s_raw;       // 32*33
        int bx = b % 192;
        int by = (b / 192) & 3;
        int z  = b / 768;
        const float* src = z ? f2 : f1;
        int p0 = bx * 32, d0 = by * 32;
        int tx = threadIdx.x & 31, ty = threadIdx.x >> 5;
        int drow = threadIdx.x >> 3;
        int px4  = threadIdx.x & 7;
        float4 v = *(const float4*)(src + (size_t)(d0 + drow) * NPIX0 + p0 + px4 * 4);
        tile[drow * 33 + px4 * 4 + 0] = v.x;
        tile[drow * 33 + px4 * 4 + 1] = v.y;
        tile[drow * 33 + px4 * 4 + 2] = v.z;
        tile[drow * 33 + px4 * 4 + 3] = v.w;
        __syncthreads();
        __half* dst = z ? g_f2h : g_f1h;
        #pragma unroll
        for (int i = 0; i < 4; i++) {
            int p = p0 + ty + 8*i;
            int d = d0 + tx;
            dst[(size_t)p * D + d] = __float2half(tile[tx * 33 + ty + 8*i]);
        }
        sig(&g_ct_prep);
        return;
    }

    if (b < B_C0) {
        // ---- coordsA: level-0 copy + x-axis triangle resize ----
        int idx = (b - B_CA) * 256 + threadIdx.x;
        if (idx < 2 * NPIX0) {
            int q = idx >> 1, ax = idx & 1;
            g_crd[idx] = crd[ax * NPIX0 + q];
        } else {
            int j = idx - 2 * NPIX0;
            if (j < 5376 * 2) {
                int p = j >> 1, ax = j & 1;
                int l, base;
                if      (p < 3072) { l = 1; base = 0;    }
                else if (p < 4608) { l = 2; base = 3072; }
                else               { l = 3; base = 4608; }
                int q  = p - base;
                int Wl = c_WL[l];
                int h  = q / Wl, w = q % Wl;
                float s   = (float)(1 << l);
                float cxx = (w + 0.5f) * s - 0.5f;
                int j0 = max(0,    (int)ceilf (cxx - s));
                int j1 = min(W0-1, (int)floorf(cxx + s));
                float sum = 0.f, acc = 0.f;
                for (int i = j0; i <= j1; i++) {
                    float wgt = 1.f - fabsf(i - cxx) / s;
                    sum += wgt;
                    acc += wgt * crd[ax * NPIX0 + h * W0 + i];
                }
                g_tmpA[p * 2 + ax] = acc / sum;
            }
        }
        sig(&g_ct_ca);
        return;
    }

    if (b < B_PL) {
        // ---- corr level 0 (needs transpose + level-0 coords only) ----
        wait2(&g_ct_prep, TR_BLOCKS, &g_ct_ca, CA_BLOCKS);
        corr_part(0, (b - B_C0) * TILE, out, s_raw);
        return;
    }

    if (b < B_CB) {
        // ---- pool levels 1..3 (needs transpose) ----
        wait1(&g_ct_prep, TR_BLOCKS);
        int idx = (b - B_PL) * 256 + threadIdx.x;
        const int POOL_N = 2016 * D;
        int m = (idx >= POOL_N);
        int q = idx - m * POOL_N;
        int d  = q & (D - 1);
        int pl = q >> 7;
        int l, pbase;
        if      (pl < 1536) { l = 1; pbase = 0;    }
        else if (pl < 1920) { l = 2; pbase = 1536; }
        else                { l = 3; pbase = 1920; }
        int pp = pl - pbase;
        int Wl = c_WL[l];
        int w  = pp % Wl, h = pp / Wl;
        __half* arr = m ? g_f2h : g_f1h;
        float acc;
        if      (l == 1) acc = poolh<2>(arr, h, w, d);
        else if (l == 2) acc = poolh<4>(arr, h, w, d);
        else             acc = poolh<8>(arr, h, w, d);
        arr[(size_t)(c_PO[l] + pp) * D + d] = __float2half(acc);
        sig(&g_ct_pool);
        return;
    }

    if (b < B_C123) {
        // ---- coordsB: y-axis resize + /2^l (needs coordsA) ----
        wait1(&g_ct_ca, CA_BLOCKS);
        int idx = (b - B_CB) * 256 + threadIdx.x;
        if (idx < 2016 * 2) {
            int p = idx >> 1, ax = idx & 1;
            int l, base, abase;
            if      (p < 1536) { l = 1; base = 0;    abase = 0;    }
            else if (p < 1920) { l = 2; base = 1536; abase = 3072; }
            else               { l = 3; base = 1920; abase = 4608; }
            int q  = p - base;
            int Wl = c_WL[l];
            int h  = q / Wl, w = q % Wl;
            float s   = (float)(1 << l);
            float cyy = (h + 0.5f) * s - 0.5f;
            int j0 = max(0,    (int)ceilf (cyy - s));
            int j1 = min(H0-1, (int)floorf(cyy + s));
            float sum = 0.f, acc = 0.f;
            for (int j = j0; j <= j1; j++) {
                float wgt = 1.f - fabsf(j - cyy) / s;
                sum += wgt;
                acc += wgt * g_tmpA[(abase + j * Wl + w) * 2 + ax];
            }
            g_crd[(c_PO[l] + q) * 2 + ax] = acc / (sum * s);
        }
        sig(&g_ct_cb);
        return;
    }

    // ---- corr levels 1..3 (needs pool + coordsB) ----
    {
        wait2(&g_ct_pool, PL_BLOCKS, &g_ct_cb, CB_BLOCKS);
        int bb = b - B_C123;
        int l, tbase;
        if      (bb < 192) { l = 1; tbase = 0;   }
        else if (bb < 240) { l = 2; tbase = 192; }
        else               { l = 3; tbase = 240; }
        corr_part(l, (bb - tbase) * TILE, out, s_raw);
    }
}

// ---------------------------------------------------------------------------
extern "C" void kernel_launch(void* const* d_in, const int* in_sizes, int n_in,
                              void* d_out, int out_size) {
    const float* f1  = (const float*)d_in[0];
    const float* f2  = (const float*)d_in[1];
    const float* crd = (const float*)d_in[2];
    float* out = (float*)d_out;

    k_reset<<<1, 1>>>();
    k_all<<<B_END, 256>>>(f1, f2, crd, out);
}

// round 8
// speedup vs baseline: 1.4777x; 1.4777x over previous
#include <cuda_runtime.h>
#include <cuda_fp16.h>

#define D      128
#define H0     64
#define W0     96
#define NPIX0  (H0*W0)        // 6144
#define NPIX_T 8160           // 6144+1536+384+96

__device__ __align__(16) __half g_f1h[NPIX_T * D];   // fp16 channel-last, all levels
__device__ __align__(16) __half g_f2h[NPIX_T * D];   // fp16 channel-last, all levels
__device__ float  g_crd [NPIX_T * 2];
__device__ float  g_tmpA[5376 * 2];                  // x-resized coords, levels 1-3

__constant__ int c_HL[4] = {64, 32, 16, 8};
__constant__ int c_WL[4] = {96, 48, 24, 12};
__constant__ int c_PO[4] = {0, 6144, 7680, 8064};
__constant__ int c_OO[4] = {0, 81*6144, 81*7680, 81*8064};

// ---------------------------------------------------------------------------
// Transpose (D,HW)->(HW,D) fp32 -> fp16, both maps. 1536 blocks.
// Load: 1x LDG.128/thread. Store: 2x half2 (4B) per thread, coalesced.
// ---------------------------------------------------------------------------
__global__ void __launch_bounds__(256) k_tr(const float* __restrict__ f1,
                                            const float* __restrict__ f2) {
    __shared__ float tile[32 * 33];
    int b  = blockIdx.x;
    int bx = b % 192;
    int by = (b / 192) & 3;
    int z  = b / 768;
    const float* src = z ? f2 : f1;
    int p0 = bx * 32, d0 = by * 32;
    int drow = threadIdx.x >> 3;
    int px4  = threadIdx.x & 7;
    float4 v = *(const float4*)(src + (size_t)(d0 + drow) * NPIX0 + p0 + px4 * 4);
    tile[drow * 33 + px4 * 4 + 0] = v.x;
    tile[drow * 33 + px4 * 4 + 1] = v.y;
    tile[drow * 33 + px4 * 4 + 2] = v.z;
    tile[drow * 33 + px4 * 4 + 3] = v.w;
    __syncthreads();
    __half* dst = z ? g_f2h : g_f1h;
    int sd = threadIdx.x & 15;       // d-pair index
    int sp = threadIdx.x >> 4;       // 0..15
    #pragma unroll
    for (int i = 0; i < 2; i++) {
        int pl = sp + 16 * i;
        float lo = tile[(sd * 2)     * 33 + pl];
        float hi = tile[(sd * 2 + 1) * 33 + pl];
        *(__half2*)(dst + (size_t)(p0 + pl) * D + d0 + sd * 2) =
            __floats2half2_rn(lo, hi);
    }
}

// ---------------------------------------------------------------------------
// coordsA: level-0 coord copy + x-axis triangle resize (levels 1-3). 90 blocks.
// ---------------------------------------------------------------------------
#define CA_ELEMS (2*NPIX0 + 5376*2)
__global__ void __launch_bounds__(256) k_coordsA(const float* __restrict__ crd) {
    int idx = blockIdx.x * 256 + threadIdx.x;
    if (idx < 2 * NPIX0) {
        int q = idx >> 1, ax = idx & 1;
        g_crd[idx] = crd[ax * NPIX0 + q];
        return;
    }
    idx -= 2 * NPIX0;
    if (idx >= 5376 * 2) return;
    int p = idx >> 1, ax = idx & 1;
    int l, base;
    if      (p < 3072) { l = 1; base = 0;    }
    else if (p < 4608) { l = 2; base = 3072; }
    else               { l = 3; base = 4608; }
    int q  = p - base;
    int Wl = c_WL[l];
    int h  = q / Wl, w = q % Wl;
    float s   = (float)(1 << l);
    float cxx = (w + 0.5f) * s - 0.5f;
    int j0 = max(0,    (int)ceilf (cxx - s));
    int j1 = min(W0-1, (int)floorf(cxx + s));
    float sum = 0.f, acc = 0.f;
    for (int i = j0; i <= j1; i++) {
        float wgt = 1.f - fabsf(i - cxx) / s;
        sum += wgt;
        acc += wgt * crd[ax * NPIX0 + h * W0 + i];
    }
    g_tmpA[p * 2 + ax] = acc / sum;
}

// ---------------------------------------------------------------------------
// coordsB: y-axis resize + /2^l. 16 blocks.
// ---------------------------------------------------------------------------
__global__ void __launch_bounds__(256) k_coordsB() {
    int idx = blockIdx.x * 256 + threadIdx.x;
    if (idx >= 2016 * 2) return;
    int p = idx >> 1, ax = idx & 1;
    int l, base, abase;
    if      (p < 1536) { l = 1; base = 0;    abase = 0;    }
    else if (p < 1920) { l = 2; base = 1536; abase = 3072; }
    else               { l = 3; base = 1920; abase = 4608; }
    int q  = p - base;
    int Wl = c_WL[l];
    int h  = q / Wl, w = q % Wl;
    float s   = (float)(1 << l);
    float cyy = (h + 0.5f) * s - 0.5f;
    int j0 = max(0,    (int)ceilf (cyy - s));
    int j1 = min(H0-1, (int)floorf(cyy + s));
    float sum = 0.f, acc = 0.f;
    for (int j = j0; j <= j1; j++) {
        float wgt = 1.f - fabsf(j - cyy) / s;
        sum += wgt;
        acc += wgt * g_tmpA[(abase + j * Wl + w) * 2 + ax];
    }
    g_crd[(c_PO[l] + q) * 2 + ax] = acc / (sum * s);
}

// ---------------------------------------------------------------------------
// pool levels 1..3, both maps (compile-time taps). 2016 blocks.
// ---------------------------------------------------------------------------
#define POOL_N (2016 * D)
template<int F>
__device__ __forceinline__ float poolh(const __half* __restrict__ src, int h, int w, int d) {
    float acc = 0.f;
    #pragma unroll
    for (int i = 0; i < F; i++)
        #pragma unroll
        for (int j = 0; j < F; j++)
            acc += __half2float(src[(size_t)((h*F + i) * W0 + (w*F + j)) * D + d]);
    return acc * (1.0f / (F * F));
}

__global__ void __launch_bounds__(256) k_pool() {
    int idx = blockIdx.x * 256 + threadIdx.x;
    int m = (idx >= POOL_N);
    int q = idx - m * POOL_N;
    int d  = q & (D - 1);
    int pl = q >> 7;
    int l, pbase;
    if      (pl < 1536) { l = 1; pbase = 0;    }
    else if (pl < 1920) { l = 2; pbase = 1536; }
    else                { l = 3; pbase = 1920; }
    int pp = pl - pbase;
    int Wl = c_WL[l];
    int w  = pp % Wl, h = pp / Wl;
    __half* arr = m ? g_f2h : g_f1h;
    float acc;
    if      (l == 1) acc = poolh<2>(arr, h, w, d);
    else if (l == 2) acc = poolh<4>(arr, h, w, d);
    else             acc = poolh<8>(arr, h, w, d);
    arr[(size_t)(c_PO[l] + pp) * D + d] = __float2half(acc);
}

// ---------------------------------------------------------------------------
// corr body (R5 scheme): warp<->pixel, 8-lane dot groups, ALU offsets.
// ---------------------------------------------------------------------------
#define TILE 8
__device__ __forceinline__ float dot8h(float4 a0, float4 a1, float4 hv) {
    const __half2* h = (const __half2*)&hv;
    float2 v0 = __half22float2(h[0]);
    float2 v1 = __half22float2(h[1]);
    float2 v2 = __half22float2(h[2]);
    float2 v3 = __half22float2(h[3]);
    return a0.x*v0.x + a0.y*v0.y + a0.z*v1.x + a0.w*v1.y
         + a1.x*v2.x + a1.y*v2.y + a1.z*v3.x + a1.w*v3.y;
}

__device__ __forceinline__ void corr_part(int l, int pix0, float* __restrict__ out) {
    int Hl = c_HL[l], Wl = c_WL[l];
    int pixoff = c_PO[l];
    int HW = Hl * Wl;

    int tid   = threadIdx.x;
    int lane  = tid & 31, warp = tid >> 5;
    int lane8 = lane & 7, grp = lane >> 3;

    __shared__ float gsh[TILE * 100];
    __shared__ float fxs[TILE], fys[TILE];
    __shared__ int   bxs[TILE], bys[TILE];

    int pix = pix0 + warp;

    const __half* f1row = g_f1h + (size_t)(pixoff + pix) * D;
    float4 ha = *(const float4*)(f1row + lane8 * 8);
    float4 hb = *(const float4*)(f1row + 64 + lane8 * 8);
    float4 a0, a1, a2, a3;
    {
        const __half2* pa = (const __half2*)&ha;
        float2 q0 = __half22float2(pa[0]), q1 = __half22float2(pa[1]);
        float2 q2 = __half22float2(pa[2]), q3 = __half22float2(pa[3]);
        a0 = make_float4(q0.x, q0.y, q1.x, q1.y);
        a1 = make_float4(q2.x, q2.y, q3.x, q3.y);
        const __half2* pb = (const __half2*)&hb;
        q0 = __half22float2(pb[0]); q1 = __half22float2(pb[1]);
        q2 = __half22float2(pb[2]); q3 = __half22float2(pb[3]);
        a2 = make_float4(q0.x, q0.y, q1.x, q1.y);
        a3 = make_float4(q2.x, q2.y, q3.x, q3.y);
    }

    float cx = 0.f, cy = 0.f;
    if (lane == 0) {
        cx = g_crd[(pixoff + pix) * 2];
        cy = g_crd[(pixoff + pix) * 2 + 1];
    }
    cx = __shfl_sync(0xffffffffu, cx, 0);
    cy = __shfl_sync(0xffffffffu, cy, 0);
    float flx = floorf(cx), fly = floorf(cy);
    int bx = (int)flx, by = (int)fly;
    if (lane == 0) {
        bxs[warp] = bx; bys[warp] = by;
        fxs[warp] = cx - flx; fys[warp] = cy - fly;
    }

    const __half* f2lane = g_f2h + (size_t)pixoff * D + lane8 * 8;
    float* gsh100 = gsh + warp * 100;

    #pragma unroll 5
    for (int i = 0; i < 25; i++) {
        int pos = i * 4 + grp;
        int u = (pos * 205) >> 11;       // pos / 10
        int t = pos - u * 10;            // pos % 10
        int px = min(max(bx + t - 4, 0), Wl - 1);
        int py = min(max(by + u - 4, 0), Hl - 1);
        const __half* row = f2lane + (py * Wl + px) * D;
        float4 h0 = *(const float4*)(row);
        float4 h1 = *(const float4*)(row + 64);
        float s = dot8h(a0, a1, h0) + dot8h(a2, a3, h1);
        s += __shfl_xor_sync(0xffffffffu, s, 4);
        s += __shfl_xor_sync(0xffffffffu, s, 2);
        s += __shfl_xor_sync(0xffffffffu, s, 1);
        if (lane8 == 0) gsh100[pos] = s;
    }
    __syncthreads();

    #pragma unroll
    for (int idx = tid; idx < 81 * TILE; idx += 256) {
        int k = idx >> 3;
        int j = idx & (TILE - 1);
        int adx = k / 9;
        int bdy = k - adx * 9;
        int t0 = bxs[j] + adx - 4;
        int u0 = bys[j] + bdy - 4;
        float wx1 = (t0 < 0 || t0 >= Wl - 1) ? 0.f : fxs[j];
        float wy1 = (u0 < 0 || u0 >= Hl - 1) ? 0.f : fys[j];
        float wx0 = 1.f - wx1, wy0 = 1.f - wy1;
        const float* g = gsh + j * 100 + bdy * 10 + adx;
        float c = wy0 * (wx0 * g[0]  + wx1 * g[1])
                + wy1 * (wx0 * g[10] + wx1 * g[11]);
        out[c_OO[l] + k * HW + pix0 + j] = c * 0.08838834764831845f; // 1/sqrt(128)
    }
}

__global__ void __launch_bounds__(256) k_corr0(float* __restrict__ out) {
    corr_part(0, blockIdx.x * TILE, out);
}

__global__ void __launch_bounds__(256) k_corr123(float* __restrict__ out) {
    int bb = blockIdx.x;
    int l, tbase;
    if      (bb < 192) { l = 1; tbase = 0;   }
    else if (bb < 240) { l = 2; tbase = 192; }
    else               { l = 3; tbase = 240; }
    corr_part(l, (bb - tbase) * TILE, out);
}

// ---------------------------------------------------------------------------
// Launch: graph-parallel branches via stream fork/join during capture.
//   stream0: TR ----------------------> [wait CA] corr0 [wait S2] (join)
//   s1:      [wait root] coordsA, coordsB
//   s2:      [wait TR] pool [wait CB] corr123
// ---------------------------------------------------------------------------
extern "C" void kernel_launch(void* const* d_in, const int* in_sizes, int n_in,
                              void* d_out, int out_size) {
    const float* f1  = (const float*)d_in[0];
    const float* f2  = (const float*)d_in[1];
    const float* crd = (const float*)d_in[2];
    float* out = (float*)d_out;

    static cudaStream_t s1 = nullptr, s2 = nullptr;
    static cudaEvent_t evRoot = nullptr, evTR = nullptr, evCA = nullptr,
                       evCB = nullptr, evS2 = nullptr;
    if (!s1) {
        cudaStreamCreateWithFlags(&s1, cudaStreamNonBlocking);
        cudaStreamCreateWithFlags(&s2, cudaStreamNonBlocking);
        cudaEventCreateWithFlags(&evRoot, cudaEventDisableTiming);
        cudaEventCreateWithFlags(&evTR,   cudaEventDisableTiming);
        cudaEventCreateWithFlags(&evCA,   cudaEventDisableTiming);
        cudaEventCreateWithFlags(&evCB,   cudaEventDisableTiming);
        cudaEventCreateWithFlags(&evS2,   cudaEventDisableTiming);
    }

    // fork
    cudaEventRecord(evRoot, 0);
    cudaStreamWaitEvent(s1, evRoot, 0);
    cudaStreamWaitEvent(s2, evRoot, 0);

    // branch B (s1): coords
    k_coordsA<<<(CA_ELEMS + 255) / 256, 256, 0, s1>>>(crd);
    cudaEventRecord(evCA, s1);
    k_coordsB<<<16, 256, 0, s1>>>();
    cudaEventRecord(evCB, s1);

    // branch A (stream 0): transpose -> corr level 0
    k_tr<<<1536, 256>>>(f1, f2);
    cudaEventRecord(evTR, 0);

    // branch C (s2): pool -> corr levels 1-3
    cudaStreamWaitEvent(s2, evTR, 0);
    k_pool<<<(2 * POOL_N) / 256, 256, 0, s2>>>();
    cudaStreamWaitEvent(s2, evCB, 0);
    k_corr123<<<252, 256, 0, s2>>>(out);
    cudaEventRecord(evS2, s2);

    // branch A continues
    cudaStreamWaitEvent(0, evCA, 0);
    k_corr0<<<768, 256>>>(out);

    // join
    cudaStreamWaitEvent(0, evS2, 0);
}

// round 9
// speedup vs baseline: 1.5706x; 1.0629x over previous
#include <cuda_runtime.h>
#include <cuda_fp16.h>

#define D      128
#define H0     64
#define W0     96
#define NPIX0  (H0*W0)        // 6144
#define NPIX_T 8160           // 6144+1536+384+96

__device__ __align__(16) __half g_f1h[NPIX_T * D];   // fp16 channel-last, all levels
__device__ __align__(16) __half g_f2h[NPIX_T * D];   // fp16 channel-last, all levels
__device__ float  g_crd [NPIX_T * 2];
__device__ float  g_tmpA[5376 * 2];                  // x-resized coords, levels 1-3

__constant__ int c_HL[4] = {64, 32, 16, 8};
__constant__ int c_WL[4] = {96, 48, 24, 12};
__constant__ int c_PO[4] = {0, 6144, 7680, 8064};
__constant__ int c_OO[4] = {0, 81*6144, 81*7680, 81*8064};

// ---------------------------------------------------------------------------
// Transpose (D,HW)->(HW,D) fp32 -> fp16, both maps. 768 blocks, each handling
// TWO 32x32 tiles (d0 and d0+32) -> 2 independent LDG.128 per thread (MLP=2).
// ---------------------------------------------------------------------------
__global__ void __launch_bounds__(256) k_tr(const float* __restrict__ f1,
                                            const float* __restrict__ f2) {
    __shared__ float tile[2][32 * 33];
    int b  = blockIdx.x;
    int bx = b % 192;            // pixel tile (32 px)
    int by = (b / 192) & 1;      // d-pair tile (64 ch)
    int z  = b / 384;            // map
    const float* src = z ? f2 : f1;
    int p0 = bx * 32, d0 = by * 64;
    int drow = threadIdx.x >> 3;       // 0..31
    int px4  = threadIdx.x & 7;        // 0..7
    const float* s0 = src + (size_t)(d0 + drow) * NPIX0 + p0 + px4 * 4;
    float4 v0 = *(const float4*)(s0);
    float4 v1 = *(const float4*)(s0 + 32 * NPIX0);
    float* t0 = &tile[0][drow * 33 + px4 * 4];
    float* t1 = &tile[1][drow * 33 + px4 * 4];
    t0[0] = v0.x; t0[1] = v0.y; t0[2] = v0.z; t0[3] = v0.w;
    t1[0] = v1.x; t1[1] = v1.y; t1[2] = v1.z; t1[3] = v1.w;
    __syncthreads();
    __half* dst = z ? g_f2h : g_f1h;
    int sd = threadIdx.x & 15;       // d-pair index within 32
    int sp = threadIdx.x >> 4;       // 0..15
    #pragma unroll
    for (int k = 0; k < 2; k++) {
        #pragma unroll
        for (int i = 0; i < 2; i++) {
            int pl = sp + 16 * i;
            float lo = tile[k][(sd * 2)     * 33 + pl];
            float hi = tile[k][(sd * 2 + 1) * 33 + pl];
            *(__half2*)(dst + (size_t)(p0 + pl) * D + d0 + k * 32 + sd * 2) =
                __floats2half2_rn(lo, hi);
        }
    }
}

// ---------------------------------------------------------------------------
// coordsA: level-0 coord copy + x-axis triangle resize (levels 1-3). 90 blocks.
// ---------------------------------------------------------------------------
#define CA_ELEMS (2*NPIX0 + 5376*2)
__global__ void __launch_bounds__(256) k_coordsA(const float* __restrict__ crd) {
    int idx = blockIdx.x * 256 + threadIdx.x;
    if (idx < 2 * NPIX0) {
        int q = idx >> 1, ax = idx & 1;
        g_crd[idx] = crd[ax * NPIX0 + q];
        return;
    }
    idx -= 2 * NPIX0;
    if (idx >= 5376 * 2) return;
    int p = idx >> 1, ax = idx & 1;
    int l, base;
    if      (p < 3072) { l = 1; base = 0;    }
    else if (p < 4608) { l = 2; base = 3072; }
    else               { l = 3; base = 4608; }
    int q  = p - base;
    int Wl = c_WL[l];
    int h  = q / Wl, w = q % Wl;
    float s   = (float)(1 << l);
    float cxx = (w + 0.5f) * s - 0.5f;
    int j0 = max(0,    (int)ceilf (cxx - s));
    int j1 = min(W0-1, (int)floorf(cxx + s));
    float sum = 0.f, acc = 0.f;
    for (int i = j0; i <= j1; i++) {
        float wgt = 1.f - fabsf(i - cxx) / s;
        sum += wgt;
        acc += wgt * crd[ax * NPIX0 + h * W0 + i];
    }
    g_tmpA[p * 2 + ax] = acc / sum;
}

// ---------------------------------------------------------------------------
// coordsB: y-axis resize + /2^l. 16 blocks.
// ---------------------------------------------------------------------------
__global__ void __launch_bounds__(256) k_coordsB() {
    int idx = blockIdx.x * 256 + threadIdx.x;
    if (idx >= 2016 * 2) return;
    int p = idx >> 1, ax = idx & 1;
    int l, base, abase;
    if      (p < 1536) { l = 1; base = 0;    abase = 0;    }
    else if (p < 1920) { l = 2; base = 1536; abase = 3072; }
    else               { l = 3; base = 1920; abase = 4608; }
    int q  = p - base;
    int Wl = c_WL[l];
    int h  = q / Wl, w = q % Wl;
    float s   = (float)(1 << l);
    float cyy = (h + 0.5f) * s - 0.5f;
    int j0 = max(0,    (int)ceilf (cyy - s));
    int j1 = min(H0-1, (int)floorf(cyy + s));
    float sum = 0.f, acc = 0.f;
    for (int j = j0; j <= j1; j++) {
        float wgt = 1.f - fabsf(j - cyy) / s;
        sum += wgt;
        acc += wgt * g_tmpA[(abase + j * Wl + w) * 2 + ax];
    }
    g_crd[(c_PO[l] + q) * 2 + ax] = acc / (sum * s);
}

// ---------------------------------------------------------------------------
// pool levels 1..3, both maps, VECTORIZED: thread <-> (pixel, 8-ch group).
// float4 (8-half) loads, fp32 accumulate, float4 store. 252 blocks.
// ---------------------------------------------------------------------------
#define POOL_T (2016 * 16)       // threads per map
template<int F>
__device__ __forceinline__ void poolv(__half* __restrict__ arr, int h, int w,
                                      int g, int dstpix) {
    const __half* src = arr;
    float2 ac0 = {0.f,0.f}, ac1 = {0.f,0.f}, ac2 = {0.f,0.f}, ac3 = {0.f,0.f};
    #pragma unroll
    for (int i = 0; i < F; i++)
        #pragma unroll
        for (int j = 0; j < F; j++) {
            float4 hv = *(const float4*)(src +
                (size_t)((h*F + i) * W0 + (w*F + j)) * D + g * 8);
            const __half2* hh = (const __half2*)&hv;
            float2 v0 = __half22float2(hh[0]);
            float2 v1 = __half22float2(hh[1]);
            float2 v2 = __half22float2(hh[2]);
            float2 v3 = __half22float2(hh[3]);
            ac0.x += v0.x; ac0.y += v0.y;
            ac1.x += v1.x; ac1.y += v1.y;
            ac2.x += v2.x; ac2.y += v2.y;
            ac3.x += v3.x; ac3.y += v3.y;
        }
    const float inv = 1.0f / (F * F);
    __half2 r[4];
    r[0] = __floats2half2_rn(ac0.x * inv, ac0.y * inv);
    r[1] = __floats2half2_rn(ac1.x * inv, ac1.y * inv);
    r[2] = __floats2half2_rn(ac2.x * inv, ac2.y * inv);
    r[3] = __floats2half2_rn(ac3.x * inv, ac3.y * inv);
    *(float4*)(arr + (size_t)dstpix * D + g * 8) = *(float4*)r;
}

__global__ void __launch_bounds__(256) k_pool() {
    int idx = blockIdx.x * 256 + threadIdx.x;
    int m = (idx >= POOL_T);
    int q = idx - m * POOL_T;
    int g  = q & 15;
    int pl = q >> 4;                 // pooled pixel 0..2015
    int l, pbase;
    if      (pl < 1536) { l = 1; pbase = 0;    }
    else if (pl < 1920) { l = 2; pbase = 1536; }
    else                { l = 3; pbase = 1920; }
    int pp = pl - pbase;
    int Wl = c_WL[l];
    int w  = pp % Wl, h = pp / Wl;
    __half* arr = m ? g_f2h : g_f1h;
    int dstpix = c_PO[l] + pp;
    if      (l == 1) poolv<2>(arr, h, w, g, dstpix);
    else if (l == 2) poolv<4>(arr, h, w, g, dstpix);
    else             poolv<8>(arr, h, w, g, dstpix);
}

// ---------------------------------------------------------------------------
// corr body (R5 scheme): warp<->pixel, 8-lane dot groups, ALU offsets.
// ---------------------------------------------------------------------------
#define TILE 8
__device__ __forceinline__ float dot8h(float4 a0, float4 a1, float4 hv) {
    const __half2* h = (const __half2*)&hv;
    float2 v0 = __half22float2(h[0]);
    float2 v1 = __half22float2(h[1]);
    float2 v2 = __half22float2(h[2]);
    float2 v3 = __half22float2(h[3]);
    return a0.x*v0.x + a0.y*v0.y + a0.z*v1.x + a0.w*v1.y
         + a1.x*v2.x + a1.y*v2.y + a1.z*v3.x + a1.w*v3.y;
}

__device__ __forceinline__ void corr_part(int l, int pix0, float* __restrict__ out) {
    int Hl = c_HL[l], Wl = c_WL[l];
    int pixoff = c_PO[l];
    int HW = Hl * Wl;

    int tid   = threadIdx.x;
    int lane  = tid & 31, warp = tid >> 5;
    int lane8 = lane & 7, grp = lane >> 3;

    __shared__ float gsh[TILE * 100];
    __shared__ float fxs[TILE], fys[TILE];
    __shared__ int   bxs[TILE], bys[TILE];

    int pix = pix0 + warp;

    const __half* f1row = g_f1h + (size_t)(pixoff + pix) * D;
    float4 ha = *(const float4*)(f1row + lane8 * 8);
    float4 hb = *(const float4*)(f1row + 64 + lane8 * 8);
    float4 a0, a1, a2, a3;
    {
        const __half2* pa = (const __half2*)&ha;
        float2 q0 = __half22float2(pa[0]), q1 = __half22float2(pa[1]);
        float2 q2 = __half22float2(pa[2]), q3 = __half22float2(pa[3]);
        a0 = make_float4(q0.x, q0.y, q1.x, q1.y);
        a1 = make_float4(q2.x, q2.y, q3.x, q3.y);
        const __half2* pb = (const __half2*)&hb;
        q0 = __half22float2(pb[0]); q1 = __half22float2(pb[1]);
        q2 = __half22float2(pb[2]); q3 = __half22float2(pb[3]);
        a2 = make_float4(q0.x, q0.y, q1.x, q1.y);
        a3 = make_float4(q2.x, q2.y, q3.x, q3.y);
    }

    float cx = 0.f, cy = 0.f;
    if (lane == 0) {
        cx = g_crd[(pixoff + pix) * 2];
        cy = g_crd[(pixoff + pix) * 2 + 1];
    }
    cx = __shfl_sync(0xffffffffu, cx, 0);
    cy = __shfl_sync(0xffffffffu, cy, 0);
    float flx = floorf(cx), fly = floorf(cy);
    int bx = (int)flx, by = (int)fly;
    if (lane == 0) {
        bxs[warp] = bx; bys[warp] = by;
        fxs[warp] = cx - flx; fys[warp] = cy - fly;
    }

    const __half* f2lane = g_f2h + (size_t)pixoff * D + lane8 * 8;
    float* gsh100 = gsh + warp * 100;

    #pragma unroll 5
    for (int i = 0; i < 25; i++) {
        int pos = i * 4 + grp;
        int u = (pos * 205) >> 11;       // pos / 10
        int t = pos - u * 10;            // pos % 10
        int px = min(max(bx + t - 4, 0), Wl - 1);
        int py = min(max(by + u - 4, 0), Hl - 1);
        const __half* row = f2lane + (py * Wl + px) * D;
        float4 h0 = *(const float4*)(row);
        float4 h1 = *(const float4*)(row + 64);
        float s = dot8h(a0, a1, h0) + dot8h(a2, a3, h1);
        s += __shfl_xor_sync(0xffffffffu, s, 4);
        s += __shfl_xor_sync(0xffffffffu, s, 2);
        s += __shfl_xor_sync(0xffffffffu, s, 1);
        if (lane8 == 0) gsh100[pos] = s;
    }
    __syncthreads();

    #pragma unroll
    for (int idx = tid; idx < 81 * TILE; idx += 256) {
        int k = idx >> 3;
        int j = idx & (TILE - 1);
        int adx = k / 9;
        int bdy = k - adx * 9;
        int t0 = bxs[j] + adx - 4;
        int u0 = bys[j] + bdy - 4;
        float wx1 = (t0 < 0 || t0 >= Wl - 1) ? 0.f : fxs[j];
        float wy1 = (u0 < 0 || u0 >= Hl - 1) ? 0.f : fys[j];
        float wx0 = 1.f - wx1, wy0 = 1.f - wy1;
        const float* g = gsh + j * 100 + bdy * 10 + adx;
        float c = wy0 * (wx0 * g[0]  + wx1 * g[1])
                + wy1 * (wx0 * g[10] + wx1 * g[11]);
        out[c_OO[l] + k * HW + pix0 + j] = c * 0.08838834764831845f; // 1/sqrt(128)
    }
}

__global__ void __launch_bounds__(256) k_corr0(float* __restrict__ out) {
    corr_part(0, blockIdx.x * TILE, out);
}

__global__ void __launch_bounds__(256) k_corr123(float* __restrict__ out) {
    int bb = blockIdx.x;
    int l, tbase;
    if      (bb < 192) { l = 1; tbase = 0;   }
    else if (bb < 240) { l = 2; tbase = 192; }
    else               { l = 3; tbase = 240; }
    corr_part(l, (bb - tbase) * TILE, out);
}

// ---------------------------------------------------------------------------
// Launch: graph-parallel branches via stream fork/join during capture.
// ---------------------------------------------------------------------------
extern "C" void kernel_launch(void* const* d_in, const int* in_sizes, int n_in,
                              void* d_out, int out_size) {
    const float* f1  = (const float*)d_in[0];
    const float* f2  = (const float*)d_in[1];
    const float* crd = (const float*)d_in[2];
    float* out = (float*)d_out;

    static cudaStream_t s1 = nullptr, s2 = nullptr;
    static cudaEvent_t evRoot = nullptr, evTR = nullptr, evCA = nullptr,
                       evCB = nullptr, evS2 = nullptr;
    if (!s1) {
        cudaStreamCreateWithFlags(&s1, cudaStreamNonBlocking);
        cudaStreamCreateWithFlags(&s2, cudaStreamNonBlocking);
        cudaEventCreateWithFlags(&evRoot, cudaEventDisableTiming);
        cudaEventCreateWithFlags(&evTR,   cudaEventDisableTiming);
        cudaEventCreateWithFlags(&evCA,   cudaEventDisableTiming);
        cudaEventCreateWithFlags(&evCB,   cudaEventDisableTiming);
        cudaEventCreateWithFlags(&evS2,   cudaEventDisableTiming);
    }

    // fork
    cudaEventRecord(evRoot, 0);
    cudaStreamWaitEvent(s1, evRoot, 0);
    cudaStreamWaitEvent(s2, evRoot, 0);

    // branch B (s1): coords
    k_coordsA<<<(CA_ELEMS + 255) / 256, 256, 0, s1>>>(crd);
    cudaEventRecord(evCA, s1);
    k_coordsB<<<16, 256, 0, s1>>>();
    cudaEventRecord(evCB, s1);

    // branch A (stream 0): transpose -> corr level 0
    k_tr<<<768, 256>>>(f1, f2);
    cudaEventRecord(evTR, 0);

    // branch C (s2): pool -> corr levels 1-3
    cudaStreamWaitEvent(s2, evTR, 0);
    k_pool<<<(2 * POOL_T) / 256, 256, 0, s2>>>();
    cudaStreamWaitEvent(s2, evCB, 0);
    k_corr123<<<252, 256, 0, s2>>>(out);
    cudaEventRecord(evS2, s2);

    // branch A continues
    cudaStreamWaitEvent(0, evCA, 0);
    k_corr0<<<768, 256>>>(out);

    // join
    cudaStreamWaitEvent(0, evS2, 0);
}